// round 5
// baseline (speedup 1.0000x reference)
#include <cuda_runtime.h>
#include <cstdint>

#define BDIM      256
#define D_F4      64       // CODE_DIM/4
#define K_CENT    4
#define N_CLASSES 1000
#define MAXB      262144
#define SPW       16       // sorted samples per warp in main kernel

// Scratch (no dynamic allocation allowed)
__device__ int g_cursor[N_CLASSES];
__device__ int g_perm[MAXB];

__device__ __forceinline__ int clamp_cls(int c) {
    return min(max(c, 0), N_CLASSES - 1);
}

// ---------------- pre-pass ----------------

__global__ void zero_kernel() {
    int t = blockIdx.x * blockDim.x + threadIdx.x;
    if (t < N_CLASSES) g_cursor[t] = 0;
}

__global__ void hist_kernel(const int* __restrict__ pred, int B) {
    __shared__ int h[N_CLASSES];
    for (int i = threadIdx.x; i < N_CLASSES; i += blockDim.x) h[i] = 0;
    __syncthreads();
    for (int i = blockIdx.x * blockDim.x + threadIdx.x; i < B;
         i += gridDim.x * blockDim.x)
        atomicAdd(&h[clamp_cls(__ldg(&pred[i]))], 1);
    __syncthreads();
    for (int i = threadIdx.x; i < N_CLASSES; i += blockDim.x)
        if (h[i]) atomicAdd(&g_cursor[i], h[i]);
}

// single-block Hillis-Steele exclusive scan over 1000 bins
__global__ void scan_kernel() {
    __shared__ int s[1024];
    int t = threadIdx.x;
    int v = (t < N_CLASSES) ? g_cursor[t] : 0;
    s[t] = v;
    __syncthreads();
    #pragma unroll
    for (int off = 1; off < 1024; off <<= 1) {
        int x = (t >= off) ? s[t - off] : 0;
        __syncthreads();
        s[t] += x;
        __syncthreads();
    }
    if (t < N_CLASSES) g_cursor[t] = s[t] - v;   // exclusive
}

__global__ void scatter_kernel(const int* __restrict__ pred, int B) {
    int i = blockIdx.x * blockDim.x + threadIdx.x;
    if (i < B) {
        int c = clamp_cls(__ldg(&pred[i]));
        int pos = atomicAdd(&g_cursor[c], 1);
        g_perm[pos] = i;
    }
}

// ---------------- main kernel (sorted order, register-cached centroids) ----

__global__ void __launch_bounds__(BDIM) sorted_kernel(
    const float4* __restrict__ codes,      // [B, 64]
    const int* __restrict__ pred,          // [B]
    const float4* __restrict__ cents,      // [1000, 4, 64]
    float* __restrict__ out,               // [B]
    int B)
{
    const int warp = (int)((blockIdx.x * (unsigned)BDIM + threadIdx.x) >> 5);
    const int lane = threadIdx.x & 31;
    const int base = warp * SPW;
    if (base >= B) return;

    // per-lane register cache of the 4 centroids of the current class
    float4 c00, c01, c10, c11, c20, c21, c30, c31;
    int cached = -1;

    const int end = min(base + SPW, B);
    for (int pos = base; pos < end; ++pos) {
        const int sidx = __ldg(&g_perm[pos]);
        const int cls  = clamp_cls(__ldg(&pred[sidx]));   // warp-uniform

        if (cls != cached) {
            const float4* __restrict__ ct = cents + (size_t)cls * (K_CENT * D_F4);
            c00 = __ldg(&ct[0 * D_F4 + lane]);  c01 = __ldg(&ct[0 * D_F4 + lane + 32]);
            c10 = __ldg(&ct[1 * D_F4 + lane]);  c11 = __ldg(&ct[1 * D_F4 + lane + 32]);
            c20 = __ldg(&ct[2 * D_F4 + lane]);  c21 = __ldg(&ct[2 * D_F4 + lane + 32]);
            c30 = __ldg(&ct[3 * D_F4 + lane]);  c31 = __ldg(&ct[3 * D_F4 + lane + 32]);
            cached = cls;
        }

        const float4* __restrict__ c = codes + (size_t)sidx * D_F4;
        const float4 a0 = __ldg(&c[lane]);
        const float4 a1 = __ldg(&c[lane + 32]);

        float s0 = fabsf(a0.x - c00.x) + fabsf(a0.y - c00.y) + fabsf(a0.z - c00.z) + fabsf(a0.w - c00.w)
                 + fabsf(a1.x - c01.x) + fabsf(a1.y - c01.y) + fabsf(a1.z - c01.z) + fabsf(a1.w - c01.w);
        float s1 = fabsf(a0.x - c10.x) + fabsf(a0.y - c10.y) + fabsf(a0.z - c10.z) + fabsf(a0.w - c10.w)
                 + fabsf(a1.x - c11.x) + fabsf(a1.y - c11.y) + fabsf(a1.z - c11.z) + fabsf(a1.w - c11.w);
        float s2 = fabsf(a0.x - c20.x) + fabsf(a0.y - c20.y) + fabsf(a0.z - c20.z) + fabsf(a0.w - c20.w)
                 + fabsf(a1.x - c21.x) + fabsf(a1.y - c21.y) + fabsf(a1.z - c21.z) + fabsf(a1.w - c21.w);
        float s3 = fabsf(a0.x - c30.x) + fabsf(a0.y - c30.y) + fabsf(a0.z - c30.z) + fabsf(a0.w - c30.w)
                 + fabsf(a1.x - c31.x) + fabsf(a1.y - c31.y) + fabsf(a1.z - c31.z) + fabsf(a1.w - c31.w);

        #pragma unroll
        for (int off = 16; off > 0; off >>= 1) {
            s0 += __shfl_xor_sync(0xFFFFFFFFu, s0, off);
            s1 += __shfl_xor_sync(0xFFFFFFFFu, s1, off);
            s2 += __shfl_xor_sync(0xFFFFFFFFu, s2, off);
            s3 += __shfl_xor_sync(0xFFFFFFFFu, s3, off);
        }

        if (lane == 0) {
            float m = fminf(fminf(s0, s1), fminf(s2, s3));
            out[sidx] = m * (1.0f / 256.0f);
        }
    }
}

// ---------------- fallback (direct gather) for B > MAXB ----------------

__global__ void __launch_bounds__(BDIM) direct_kernel(
    const float4* __restrict__ codes, const int* __restrict__ pred,
    const float4* __restrict__ cents, float* __restrict__ out, int B)
{
    const int warp = (int)((blockIdx.x * (unsigned)BDIM + threadIdx.x) >> 5);
    const int lane = threadIdx.x & 31;
    if (warp >= B) return;
    const float4* __restrict__ c = codes + (size_t)warp * D_F4;
    const float4 a0 = __ldg(&c[lane]);
    const float4 a1 = __ldg(&c[lane + 32]);
    int cls = clamp_cls(__ldg(&pred[warp]));
    const float4* __restrict__ ct = cents + (size_t)cls * (K_CENT * D_F4);
    float s[4];
    #pragma unroll
    for (int k = 0; k < 4; ++k) {
        float4 b0 = __ldg(&ct[k * D_F4 + lane]);
        float4 b1 = __ldg(&ct[k * D_F4 + lane + 32]);
        s[k] = fabsf(a0.x - b0.x) + fabsf(a0.y - b0.y) + fabsf(a0.z - b0.z) + fabsf(a0.w - b0.w)
             + fabsf(a1.x - b1.x) + fabsf(a1.y - b1.y) + fabsf(a1.z - b1.z) + fabsf(a1.w - b1.w);
    }
    #pragma unroll
    for (int off = 16; off > 0; off >>= 1) {
        s[0] += __shfl_xor_sync(0xFFFFFFFFu, s[0], off);
        s[1] += __shfl_xor_sync(0xFFFFFFFFu, s[1], off);
        s[2] += __shfl_xor_sync(0xFFFFFFFFu, s[2], off);
        s[3] += __shfl_xor_sync(0xFFFFFFFFu, s[3], off);
    }
    if (lane == 0)
        out[warp] = fminf(fminf(s[0], s[1]), fminf(s[2], s[3])) * (1.0f / 256.0f);
}

// ---------------- launch ----------------

extern "C" void kernel_launch(void* const* d_in, const int* in_sizes, int n_in,
                              void* d_out, int out_size)
{
    // Identify inputs by element count (order-proof):
    int i_codes = 0, i_pred = 0, i_cent = 0;
    for (int i = 1; i < n_in; ++i) {
        if (in_sizes[i] > in_sizes[i_codes]) i_codes = i;
        if (in_sizes[i] < in_sizes[i_pred])  i_pred  = i;
    }
    for (int i = 0; i < n_in; ++i)
        if (i != i_codes && i != i_pred) { i_cent = i; break; }

    const float4* codes = (const float4*)d_in[i_codes];
    const int*    pred  = (const int*)d_in[i_pred];
    const float4* cents = (const float4*)d_in[i_cent];
    float*        out   = (float*)d_out;
    const int B = in_sizes[i_pred];

    if (B > MAXB) {
        const int grid = (B + (BDIM / 32) - 1) / (BDIM / 32);
        direct_kernel<<<grid, BDIM>>>(codes, pred, cents, out, B);
        return;
    }

    // 1) zero class cursors (must happen every graph replay)
    zero_kernel<<<(N_CLASSES + 255) / 256, 256>>>();
    // 2) histogram into g_cursor
    hist_kernel<<<512, 256>>>(pred, B);
    // 3) exclusive scan -> start offsets
    scan_kernel<<<1, 1024>>>();
    // 4) scatter -> class-sorted permutation
    scatter_kernel<<<(B + 255) / 256, 256>>>(pred, B);
    // 5) main compute in sorted order
    const int warps = (B + SPW - 1) / SPW;
    const int grid  = (warps + (BDIM / 32) - 1) / (BDIM / 32);
    sorted_kernel<<<grid, BDIM>>>(codes, pred, cents, out, B);
}

// round 7
// speedup vs baseline: 1.3053x; 1.3053x over previous
#include <cuda_runtime.h>
#include <cstdint>

#define BDIM      256
#define D_F4      64        // CODE_DIM/4
#define K_CENT    4
#define N_CLASSES 1000
#define MAXB      262144    // = 2^18; perm packs sidx in 18 bits
#define SPW       16        // sorted samples per warp in main kernel
#define PAD       32        // 32 ints = 128B stride between class counters

// Scratch (static — no dynamic allocation allowed)
__device__ int g_cursor[N_CLASSES * PAD];   // 128B-strided counters/offsets
__device__ int g_perm[MAXB];                // packed (cls<<18)|sidx

__device__ __forceinline__ int clamp_cls(int c) {
    return min(max(c, 0), N_CLASSES - 1);
}

// ---------------- pre-pass ----------------

__global__ void zero_kernel() {
    int t = blockIdx.x * blockDim.x + threadIdx.x;
    if (t < N_CLASSES * PAD) g_cursor[t] = 0;
}

__global__ void hist_kernel(const int* __restrict__ pred, int B) {
    __shared__ int h[N_CLASSES];
    for (int i = threadIdx.x; i < N_CLASSES; i += blockDim.x) h[i] = 0;
    __syncthreads();
    for (int i = blockIdx.x * blockDim.x + threadIdx.x; i < B;
         i += gridDim.x * blockDim.x)
        atomicAdd(&h[clamp_cls(__ldg(&pred[i]))], 1);
    __syncthreads();
    for (int i = threadIdx.x; i < N_CLASSES; i += blockDim.x)
        if (h[i]) atomicAdd(&g_cursor[i * PAD], h[i]);   // 128B-strided -> spread over LTS
}

// single-block Hillis-Steele exclusive scan over 1000 bins
__global__ void scan_kernel() {
    __shared__ int s[1024];
    int t = threadIdx.x;
    int v = (t < N_CLASSES) ? g_cursor[t * PAD] : 0;
    s[t] = v;
    __syncthreads();
    #pragma unroll
    for (int off = 1; off < 1024; off <<= 1) {
        int x = (t >= off) ? s[t - off] : 0;
        __syncthreads();
        s[t] += x;
        __syncthreads();
    }
    if (t < N_CLASSES) g_cursor[t * PAD] = s[t] - v;   // exclusive start offsets
}

__global__ void scatter_kernel(const int* __restrict__ pred, int B) {
    int i = blockIdx.x * blockDim.x + threadIdx.x;
    if (i < B) {
        int c = clamp_cls(__ldg(&pred[i]));
        int pos = atomicAdd(&g_cursor[c * PAD], 1);    // strided -> low contention
        g_perm[pos] = (c << 18) | i;                   // pack class + sample idx
    }
}

// ---------------- main kernel (sorted order, register-cached centroids) ----

__global__ void __launch_bounds__(BDIM) sorted_kernel(
    const float4* __restrict__ codes,      // [B, 64]
    const float4* __restrict__ cents,      // [1000, 4, 64]
    float* __restrict__ out,               // [B]
    int B)
{
    const int warp = (int)((blockIdx.x * (unsigned)BDIM + threadIdx.x) >> 5);
    const int lane = threadIdx.x & 31;
    const int base = warp * SPW;
    if (base >= B) return;

    // per-lane register cache of the 4 centroids of the current class
    float4 c00, c01, c10, c11, c20, c21, c30, c31;
    int cached = -1;

    const int end = min(base + SPW, B);
    for (int pos = base; pos < end; ++pos) {
        const int packed = __ldg(&g_perm[pos]);
        const int sidx = packed & 0x3FFFF;
        const int cls  = packed >> 18;                 // warp-uniform within runs

        if (cls != cached) {
            const float4* __restrict__ ct = cents + (size_t)cls * (K_CENT * D_F4);
            c00 = __ldg(&ct[0 * D_F4 + lane]);  c01 = __ldg(&ct[0 * D_F4 + lane + 32]);
            c10 = __ldg(&ct[1 * D_F4 + lane]);  c11 = __ldg(&ct[1 * D_F4 + lane + 32]);
            c20 = __ldg(&ct[2 * D_F4 + lane]);  c21 = __ldg(&ct[2 * D_F4 + lane + 32]);
            c30 = __ldg(&ct[3 * D_F4 + lane]);  c31 = __ldg(&ct[3 * D_F4 + lane + 32]);
            cached = cls;
        }

        const float4* __restrict__ c = codes + (size_t)sidx * D_F4;
        const float4 a0 = __ldg(&c[lane]);
        const float4 a1 = __ldg(&c[lane + 32]);

        float s0 = fabsf(a0.x - c00.x) + fabsf(a0.y - c00.y) + fabsf(a0.z - c00.z) + fabsf(a0.w - c00.w)
                 + fabsf(a1.x - c01.x) + fabsf(a1.y - c01.y) + fabsf(a1.z - c01.z) + fabsf(a1.w - c01.w);
        float s1 = fabsf(a0.x - c10.x) + fabsf(a0.y - c10.y) + fabsf(a0.z - c10.z) + fabsf(a0.w - c10.w)
                 + fabsf(a1.x - c11.x) + fabsf(a1.y - c11.y) + fabsf(a1.z - c11.z) + fabsf(a1.w - c11.w);
        float s2 = fabsf(a0.x - c20.x) + fabsf(a0.y - c20.y) + fabsf(a0.z - c20.z) + fabsf(a0.w - c20.w)
                 + fabsf(a1.x - c21.x) + fabsf(a1.y - c21.y) + fabsf(a1.z - c21.z) + fabsf(a1.w - c21.w);
        float s3 = fabsf(a0.x - c30.x) + fabsf(a0.y - c30.y) + fabsf(a0.z - c30.z) + fabsf(a0.w - c30.w)
                 + fabsf(a1.x - c31.x) + fabsf(a1.y - c31.y) + fabsf(a1.z - c31.z) + fabsf(a1.w - c31.w);

        #pragma unroll
        for (int off = 16; off > 0; off >>= 1) {
            s0 += __shfl_xor_sync(0xFFFFFFFFu, s0, off);
            s1 += __shfl_xor_sync(0xFFFFFFFFu, s1, off);
            s2 += __shfl_xor_sync(0xFFFFFFFFu, s2, off);
            s3 += __shfl_xor_sync(0xFFFFFFFFu, s3, off);
        }

        if (lane == 0) {
            float m = fminf(fminf(s0, s1), fminf(s2, s3));
            out[sidx] = m * (1.0f / 256.0f);
        }
    }
}

// ---------------- fallback (direct gather) for B > MAXB ----------------

__global__ void __launch_bounds__(BDIM) direct_kernel(
    const float4* __restrict__ codes, const int* __restrict__ pred,
    const float4* __restrict__ cents, float* __restrict__ out, int B)
{
    const int warp = (int)((blockIdx.x * (unsigned)BDIM + threadIdx.x) >> 5);
    const int lane = threadIdx.x & 31;
    if (warp >= B) return;
    const float4* __restrict__ c = codes + (size_t)warp * D_F4;
    const float4 a0 = __ldg(&c[lane]);
    const float4 a1 = __ldg(&c[lane + 32]);
    int cls = clamp_cls(__ldg(&pred[warp]));
    const float4* __restrict__ ct = cents + (size_t)cls * (K_CENT * D_F4);
    float s[4];
    #pragma unroll
    for (int k = 0; k < 4; ++k) {
        float4 b0 = __ldg(&ct[k * D_F4 + lane]);
        float4 b1 = __ldg(&ct[k * D_F4 + lane + 32]);
        s[k] = fabsf(a0.x - b0.x) + fabsf(a0.y - b0.y) + fabsf(a0.z - b0.z) + fabsf(a0.w - b0.w)
             + fabsf(a1.x - b1.x) + fabsf(a1.y - b1.y) + fabsf(a1.z - b1.z) + fabsf(a1.w - b1.w);
    }
    #pragma unroll
    for (int off = 16; off > 0; off >>= 1) {
        s[0] += __shfl_xor_sync(0xFFFFFFFFu, s[0], off);
        s[1] += __shfl_xor_sync(0xFFFFFFFFu, s[1], off);
        s[2] += __shfl_xor_sync(0xFFFFFFFFu, s[2], off);
        s[3] += __shfl_xor_sync(0xFFFFFFFFu, s[3], off);
    }
    if (lane == 0)
        out[warp] = fminf(fminf(s[0], s[1]), fminf(s[2], s[3])) * (1.0f / 256.0f);
}

// ---------------- launch ----------------

extern "C" void kernel_launch(void* const* d_in, const int* in_sizes, int n_in,
                              void* d_out, int out_size)
{
    // Identify inputs by element count (order-proof):
    int i_codes = 0, i_pred = 0, i_cent = 0;
    for (int i = 1; i < n_in; ++i) {
        if (in_sizes[i] > in_sizes[i_codes]) i_codes = i;
        if (in_sizes[i] < in_sizes[i_pred])  i_pred  = i;
    }
    for (int i = 0; i < n_in; ++i)
        if (i != i_codes && i != i_pred) { i_cent = i; break; }

    const float4* codes = (const float4*)d_in[i_codes];
    const int*    pred  = (const int*)d_in[i_pred];
    const float4* cents = (const float4*)d_in[i_cent];
    float*        out   = (float*)d_out;
    const int B = in_sizes[i_pred];

    if (B > MAXB) {
        const int grid = (B + (BDIM / 32) - 1) / (BDIM / 32);
        direct_kernel<<<grid, BDIM>>>(codes, pred, cents, out, B);
        return;
    }

    // 1) zero strided class cursors (every replay)
    zero_kernel<<<(N_CLASSES * PAD + 255) / 256, 256>>>();
    // 2) histogram into strided cursors
    hist_kernel<<<256, 256>>>(pred, B);
    // 3) exclusive scan -> start offsets
    scan_kernel<<<1, 1024>>>();
    // 4) scatter -> class-sorted packed permutation
    scatter_kernel<<<(B + 255) / 256, 256>>>(pred, B);
    // 5) main compute in sorted order
    const int warps = (B + SPW - 1) / SPW;
    const int grid  = (warps + (BDIM / 32) - 1) / (BDIM / 32);
    sorted_kernel<<<grid, BDIM>>>(codes, cents, out, B);
}